// round 10
// baseline (speedup 1.0000x reference)
#include <cuda_runtime.h>
#include <math.h>

#define HDC_D      10000
#define HDC_T      2048
#define HDC_LEVELS 100
#define TPB        256     // 8 warps share one tile; each warp = distinct time-chunk
#define WCOLS      128     // columns per block tile (4 per thread)
#define EFFC       126     // effective output columns per block (2-col halo)
#define NBD        80      // ceil(10000 / 126)
#define NTY        8       // grid.y
#define NT         64      // time-chunks (8 per block)
#define MTOT       2046    // T - 2 product terms
#define MCHUNK     32      // terms per chunk (32*64 = 2048 >= 2046)
#define SIDX_N     (8 * MCHUNK + 2)   // 258 idx rows staged per block

// partial sums, TRANSPOSED layout [d][NT] so the epilogue reads float4s
__device__ float g_partial[HDC_D * NT];

typedef unsigned long long ull;
typedef unsigned int uint;

// ---------- packed f32x2 helpers (Blackwell) ----------
__device__ __forceinline__ ull pk2(float lo, float hi) {
    ull r; asm("mov.b64 %0, {%1, %2};" : "=l"(r) : "f"(lo), "f"(hi)); return r;
}
__device__ __forceinline__ void up2(ull v, float& lo, float& hi) {
    asm("mov.b64 {%0, %1}, %2;" : "=f"(lo), "=f"(hi) : "l"(v));
}
__device__ __forceinline__ ull fma2(ull a, ull b, ull c) {
    ull d; asm("fma.rn.f32x2 %0, %1, %2, %3;" : "=l"(d) : "l"(a), "l"(b), "l"(c)); return d;
}
__device__ __forceinline__ ull mul2(ull a, ull b) {
    ull d; asm("mul.rn.f32x2 %0, %1, %2;" : "=l"(d) : "l"(a), "l"(b)); return d;
}

__device__ __forceinline__ int wrapD(int g) {
    if (g < 0)       g += HDC_D;
    if (g >= HDC_D)  g -= HDC_D;
    return g;
}

__global__ void __launch_bounds__(TPB)
hv_kernel(const float* __restrict__ inp,
          const float* __restrict__ keys,
          const float* __restrict__ level) {
    // sign tile: byte = 1 if level < 0 else 0.  12.8 KB + 2.1 KB static smem.
    __shared__ unsigned char tile8[HDC_LEVELS * WCOLS];
    __shared__ ushort4 sidx[SIDX_N];

    const int tid  = threadIdx.x;
    const int warp = tid >> 5;
    const int lane = tid & 31;

    // --- fused idx prep: this block's t-slice -> shared, pre-scaled by 128 B ---
    const int t_base = 8 * MCHUNK * blockIdx.y;
    const int scnt   = min(SIDX_N, HDC_T - t_base);
    for (int i = tid; i < scnt; i += TPB) {
        float4 v = reinterpret_cast<const float4*>(inp)[t_base + i];
        // jnp.round = round half to even -> __float2int_rn
        int i0 = min(max(__float2int_rn(v.x * 99.0f), 0), 99);
        int i1 = min(max(__float2int_rn(v.y * 99.0f), 0), 99);
        int i2 = min(max(__float2int_rn(v.z * 99.0f), 0), 99);
        int i3 = min(max(__float2int_rn(v.w * 99.0f), 0), 99);
        sidx[i] = make_ushort4((unsigned short)(i0 * WCOLS), (unsigned short)(i1 * WCOLS),
                               (unsigned short)(i2 * WCOLS), (unsigned short)(i3 * WCOLS));
    }

    // --- stage 100 x 128 sign-byte tile (4 cols per thread-iter, STS.32) ---
    const int gstart = blockIdx.x * EFFC - 2;   // even
    for (int i = tid; i < HDC_LEVELS * (WCOLS / 4); i += TPB) {
        int row = i >> 5;          // / 32
        int q   = i & 31;          // quad of 4 columns
        int ga = wrapD(gstart + 4 * q);
        int gb = wrapD(gstart + 4 * q + 2);
        float2 A = *reinterpret_cast<const float2*>(level + row * HDC_D + ga);
        float2 B = *reinterpret_cast<const float2*>(level + row * HDC_D + gb);
        uint w =  (__float_as_uint(A.x) >> 31)
               | ((__float_as_uint(A.y) >> 31) << 8)
               | ((__float_as_uint(B.x) >> 31) << 16)
               | ((__float_as_uint(B.y) >> 31) << 24);
        *reinterpret_cast<uint*>(tile8 + row * WCOLS + 4 * q) = w;
    }

    // --- per-thread packed key sign bytes, one word per channel ---
    const int p0 = gstart + 4 * lane;   // even
    uint K[4];
    #pragma unroll
    for (int c = 0; c < 4; c++) {
        uint w = 0;
        #pragma unroll
        for (int j = 0; j < 4; j++) {
            int col = wrapD(p0 + j);
            w |= (__float_as_uint(keys[c * HDC_D + col]) >> 31) << (8 * j);
        }
        K[c] = w;
    }
    __syncthreads();

    const int ct    = blockIdx.y * 8 + warp;
    const int m0    = ct * MCHUNK;
    const int iters = min(MCHUNK, MTOT - m0) + 2;
    const int soff  = warp * MCHUNK;            // m0 - t_base
    const unsigned char* tp = tile8 + 4 * lane;

    const ull Cm2 = pk2(-2.0f, -2.0f);
    const ull C4  = pk2( 4.0f,  4.0f);

    ull h1lo = 0, h1hi = 0, h2lo = 0, h2hi = 0, acclo = 0, acchi = 0;

    #pragma unroll 4
    for (int j = 0; j < iters; j++) {
        ushort4 u = sidx[soff + j];             // broadcast LDS.64
        uint R0 = *reinterpret_cast<const uint*>(tp + u.x);
        uint R1 = *reinterpret_cast<const uint*>(tp + u.y);
        uint R2 = *reinterpret_cast<const uint*>(tp + u.z);
        uint R3 = *reinterpret_cast<const uint*>(tp + u.w);

        // per-byte count of negative products; bytes <= 4, no carry
        uint P = (R0 ^ K[0]) + (R1 ^ K[1]) + (R2 ^ K[2]) + (R3 ^ K[3]);
        int s0 = __dp4a((int)P, 0x00000001, 0);
        int s1 = __dp4a((int)P, 0x00000100, 0);
        int s2 = __dp4a((int)P, 0x00010000, 0);
        int s3 = __dp4a((int)P, 0x01000000, 0);

        // hv = 4 - 2*s  (exact)
        ull Hlo = fma2(pk2((float)s0, (float)s1), Cm2, C4);
        ull Hhi = fma2(pk2((float)s2, (float)s3), Cm2, C4);

        // a = hv[t-2] at d-2: cols (c0,c1) <- lane-1's (c2,c3); (c2,c3) <- own (c0,c1)
        ull a_lo = __shfl_up_sync(0xffffffffu, h2hi, 1);
        ull a_hi = h2lo;
        // b = hv[t-1] at d-1: c0 <- lane-1's c3; c1,c2,c3 <- own c0,c1,c2
        float h1hx, h1hy, h1lx, h1ly;
        up2(h1hi, h1hx, h1hy);
        up2(h1lo, h1lx, h1ly);
        float bl0 = __shfl_up_sync(0xffffffffu, h1hy, 1);
        ull b_lo = pk2(bl0, h1lx);
        ull b_hi = pk2(h1ly, h1hx);

        acclo = fma2(mul2(a_lo, b_lo), Hlo, acclo);  // zero history -> first 2 iters add 0
        acchi = fma2(mul2(a_hi, b_hi), Hhi, acchi);

        h2lo = h1lo; h2hi = h1hi;
        h1lo = Hlo;  h1hi = Hhi;
    }

    // transposed scatter: g_partial[d][ct]. lane0 owns only its hi pair.
    float alx, aly, ahx, ahy;
    up2(acclo, alx, aly);
    up2(acchi, ahx, ahy);
    if (lane == 0) {
        g_partial[(p0 + 2) * NT + ct] = ahx;
        g_partial[(p0 + 3) * NT + ct] = ahy;
    } else if (p0 < HDC_D) {
        g_partial[(p0    ) * NT + ct] = alx;
        g_partial[(p0 + 1) * NT + ct] = aly;
        g_partial[(p0 + 2) * NT + ct] = ahx;
        g_partial[(p0 + 3) * NT + ct] = ahy;
    }
}

// 4 roles per column d; 128-thread block covers 32 columns.
// role0: f1,          partials  0..15
// role1: f3+f4+f5,    partials 16..31
// role2: f6+f7+f8,    partials 32..47
// role3: h6+f9,       partials 48..63
__global__ void __launch_bounds__(128)
epilogue_kernel(const float* __restrict__ feat,
                const float* __restrict__ W3,
                const float* __restrict__ b3,
                const float* __restrict__ W6,
                const float* __restrict__ b6,
                float* __restrict__ out) {
    __shared__ float fac[4][32];
    __shared__ float ps[4][32];

    const int lane = threadIdx.x & 31;
    const int role = threadIdx.x >> 5;
    const int d    = blockIdx.x * 32 + lane;
    const bool valid = d < HDC_D;

    const int S[8] = {0, 9, 12, 15, 18, 21, 24, 27};

    if (valid) {
        // ---- this role's 16 partials (4 x float4, exact integers -> any order) ----
        const float4* pp = reinterpret_cast<const float4*>(g_partial + d * NT) + role * 4;
        float4 a0 = pp[0], a1 = pp[1], a2 = pp[2], a3 = pp[3];
        float s = ((a0.x + a0.y) + (a0.z + a0.w)) + ((a1.x + a1.y) + (a1.z + a1.w))
                + ((a2.x + a2.y) + (a2.z + a2.w)) + ((a3.x + a3.y) + (a3.z + a3.w));
        ps[role][lane] = s;

        // ---- this role's factor ----
        float f;
        if (role == 0) {
            const float* w = W3 + (0 * HDC_D + d) * 3;
            float p = w[0] * feat[S[0]] + w[1] * feat[S[0] + 1] + w[2] * feat[S[0] + 2];
            f = cosf(p + b3[0 * HDC_D + d]) * sinf(p);
        } else if (role == 3) {
            const float* w = W3 + (7 * HDC_D + d) * 3;
            float p = w[0] * feat[S[7]] + w[1] * feat[S[7] + 1] + w[2] * feat[S[7] + 2];
            float f9 = cosf(p + b3[7 * HDC_D + d]) * sinf(p);
            float p6 = 0.0f;
            #pragma unroll
            for (int i = 0; i < 6; i++) p6 += W6[d * 6 + i] * feat[3 + i];
            float h6 = cosf(p6 + b6[d]) * sinf(p6);
            f = h6 + f9;
        } else {
            int k0 = (role == 1) ? 1 : 4;
            float h[3];
            #pragma unroll
            for (int j = 0; j < 3; j++) {
                int k = k0 + j;
                const float* w = W3 + (k * HDC_D + d) * 3;
                float p = w[0] * feat[S[k]] + w[1] * feat[S[k] + 1] + w[2] * feat[S[k] + 2];
                h[j] = cosf(p + b3[k * HDC_D + d]) * sinf(p);
            }
            f = (h[0] + h[1]) + h[2];   // reference left-assoc order
        }
        fac[role][lane] = f;
    }
    __syncthreads();

    if (role == 0 && valid) {
        float s = (ps[0][lane] + ps[1][lane]) + (ps[2][lane] + ps[3][lane]);  // exact
        // match reference multiply order exactly
        float o = s * fac[0][lane];
        o *= fac[3][lane];
        o *= fac[1][lane];
        o *= fac[2][lane];
        out[d] = (o > 0.0f) ? 1.0f : -1.0f;
    }
}

extern "C" void kernel_launch(void* const* d_in, const int* in_sizes, int n_in,
                              void* d_out, int out_size) {
    const float* inp   = (const float*)d_in[0];
    const float* feat  = (const float*)d_in[1];
    const float* keys  = (const float*)d_in[2];
    const float* level = (const float*)d_in[3];
    const float* W3    = (const float*)d_in[4];
    const float* b3    = (const float*)d_in[5];
    const float* W6    = (const float*)d_in[6];
    const float* b6    = (const float*)d_in[7];
    float* out = (float*)d_out;

    dim3 grid(NBD, NTY);
    hv_kernel<<<grid, TPB>>>(inp, keys, level);
    epilogue_kernel<<<(HDC_D + 31) / 32, 128>>>(feat, W3, b3, W6, b6, out);
}

// round 12
// speedup vs baseline: 1.1488x; 1.1488x over previous
#include <cuda_runtime.h>
#include <math.h>

#define HDC_D      10000
#define HDC_T      2048
#define HDC_LEVELS 100
#define TPB        256     // 8 warps share one tile; each warp = distinct time-chunk
#define WCOLS      128     // columns per block tile (4 per thread)
#define EFFC       126     // effective output columns per block (2-col halo)
#define NBD        80      // ceil(10000 / 126)
#define NTY        5
#define NT         40      // time-chunks (8 per block)
#define MTOT       2046    // T - 2 product terms
#define MCHUNK     52      // terms per chunk (52*40 = 2080 >= 2046)
#define SIDX_N     (8 * MCHUNK + 2)   // 418 idx rows staged per block
#define HV_BLOCKS  (NBD * NTY)        // 400
#define FAC_BLOCKS 40                 // 40*256 = 10240 >= 10000

// partial sums, TRANSPOSED layout [d][NT] so the final kernel reads float4s
__device__ float g_partial[HDC_D * NT];
__device__ float g_factor[HDC_D];

typedef unsigned long long ull;
typedef unsigned int uint;

// ---------- packed f32x2 helpers (Blackwell) ----------
__device__ __forceinline__ ull pk2(float lo, float hi) {
    ull r; asm("mov.b64 %0, {%1, %2};" : "=l"(r) : "f"(lo), "f"(hi)); return r;
}
__device__ __forceinline__ void up2(ull v, float& lo, float& hi) {
    asm("mov.b64 {%0, %1}, %2;" : "=f"(lo), "=f"(hi) : "l"(v));
}
__device__ __forceinline__ ull fma2(ull a, ull b, ull c) {
    ull d; asm("fma.rn.f32x2 %0, %1, %2, %3;" : "=l"(d) : "l"(a), "l"(b), "l"(c)); return d;
}
__device__ __forceinline__ ull mul2(ull a, ull b) {
    ull d; asm("mul.rn.f32x2 %0, %1, %2;" : "=l"(d) : "l"(a), "l"(b)); return d;
}

__device__ __forceinline__ int wrapD(int g) {
    if (g < 0)       g += HDC_D;
    if (g >= HDC_D)  g -= HDC_D;
    return g;
}

// Fused kernel: blocks [0, HV_BLOCKS) do hv time-chunks; blocks
// [HV_BLOCKS, HV_BLOCKS+FAC_BLOCKS) compute the hv-independent trig factor.
// They run concurrently, so the factor's DRAM latency hides under hv compute.
__global__ void __launch_bounds__(TPB)
fused_kernel(const float* __restrict__ inp,
             const float* __restrict__ keys,
             const float* __restrict__ level,
             const float* __restrict__ feat,
             const float* __restrict__ W3,
             const float* __restrict__ b3,
             const float* __restrict__ W6,
             const float* __restrict__ b6) {
    __shared__ unsigned char tile8[HDC_LEVELS * WCOLS];  // sign bytes
    __shared__ ushort4 sidx[SIDX_N];

    const int tid = threadIdx.x;

    if (blockIdx.x >= HV_BLOCKS) {
        // ================= factor blocks =================
        int d = (blockIdx.x - HV_BLOCKS) * TPB + tid;
        if (d < HDC_D) {
            const int S[8] = {0, 9, 12, 15, 18, 21, 24, 27};
            // front-batch independent loads
            float w3v[8][3], b3v[8];
            #pragma unroll
            for (int k = 0; k < 8; k++) {
                const float* w = W3 + (k * HDC_D + d) * 3;
                w3v[k][0] = w[0]; w3v[k][1] = w[1]; w3v[k][2] = w[2];
                b3v[k] = b3[k * HDC_D + d];
            }
            float w6v[6];
            #pragma unroll
            for (int i = 0; i < 6; i++) w6v[i] = W6[d * 6 + i];
            float b6v = b6[d];
            float fv[30];
            #pragma unroll
            for (int i = 0; i < 30; i++) fv[i] = feat[i];

            float h[8];
            #pragma unroll
            for (int k = 0; k < 8; k++) {
                float p = w3v[k][0] * fv[S[k]] + w3v[k][1] * fv[S[k] + 1]
                        + w3v[k][2] * fv[S[k] + 2];
                h[k] = cosf(p + b3v[k]) * sinf(p);
            }
            float p6 = 0.0f;
            #pragma unroll
            for (int i = 0; i < 6; i++) p6 += w6v[i] * fv[3 + i];
            float h6 = cosf(p6 + b6v) * sinf(p6);

            // factor product in reference's factor order (sign-exact vs s*...)
            float F = h[0];
            F *= (h6 + h[7]);
            F *= (h[1] + h[2]) + h[3];
            F *= (h[4] + h[5]) + h[6];
            g_factor[d] = F;
        }
        return;
    }

    // ================= hv blocks =================
    const int bx   = blockIdx.x % NBD;
    const int by   = blockIdx.x / NBD;
    const int warp = tid >> 5;
    const int lane = tid & 31;

    // --- fused idx prep: this block's t-slice -> shared, pre-scaled by 128 B ---
    const int t_base = 8 * MCHUNK * by;
    const int scnt   = min(SIDX_N, HDC_T - t_base);
    for (int i = tid; i < scnt; i += TPB) {
        float4 v = reinterpret_cast<const float4*>(inp)[t_base + i];
        // jnp.round = round half to even -> __float2int_rn
        int i0 = min(max(__float2int_rn(v.x * 99.0f), 0), 99);
        int i1 = min(max(__float2int_rn(v.y * 99.0f), 0), 99);
        int i2 = min(max(__float2int_rn(v.z * 99.0f), 0), 99);
        int i3 = min(max(__float2int_rn(v.w * 99.0f), 0), 99);
        sidx[i] = make_ushort4((unsigned short)(i0 * WCOLS), (unsigned short)(i1 * WCOLS),
                               (unsigned short)(i2 * WCOLS), (unsigned short)(i3 * WCOLS));
    }

    // --- stage 100 x 128 sign-byte tile ---
    const int gstart = bx * EFFC - 2;   // even
    for (int i = tid; i < HDC_LEVELS * (WCOLS / 4); i += TPB) {
        int row = i >> 5;
        int q   = i & 31;
        int ga = wrapD(gstart + 4 * q);
        int gb = wrapD(gstart + 4 * q + 2);
        float2 A = *reinterpret_cast<const float2*>(level + row * HDC_D + ga);
        float2 B = *reinterpret_cast<const float2*>(level + row * HDC_D + gb);
        uint w =  (__float_as_uint(A.x) >> 31)
               | ((__float_as_uint(A.y) >> 31) << 8)
               | ((__float_as_uint(B.x) >> 31) << 16)
               | ((__float_as_uint(B.y) >> 31) << 24);
        *reinterpret_cast<uint*>(tile8 + row * WCOLS + 4 * q) = w;
    }

    // --- per-thread packed key sign bytes, one word per channel ---
    const int p0 = gstart + 4 * lane;   // even
    uint K[4];
    #pragma unroll
    for (int c = 0; c < 4; c++) {
        uint w = 0;
        #pragma unroll
        for (int j = 0; j < 4; j++) {
            int col = wrapD(p0 + j);
            w |= (__float_as_uint(keys[c * HDC_D + col]) >> 31) << (8 * j);
        }
        K[c] = w;
    }
    __syncthreads();

    const int ct    = by * 8 + warp;
    const int m0    = ct * MCHUNK;
    const int iters = min(MCHUNK, MTOT - m0) + 2;
    const int soff  = warp * MCHUNK;
    const unsigned char* tp = tile8 + 4 * lane;

    const ull Cm2 = pk2(-2.0f, -2.0f);
    const ull C4  = pk2( 4.0f,  4.0f);

    ull h1lo = 0, h1hi = 0, h2lo = 0, h2hi = 0, acclo = 0, acchi = 0;

    #pragma unroll 4
    for (int j = 0; j < iters; j++) {
        ushort4 u = sidx[soff + j];             // broadcast LDS.64
        uint R0 = *reinterpret_cast<const uint*>(tp + u.x);
        uint R1 = *reinterpret_cast<const uint*>(tp + u.y);
        uint R2 = *reinterpret_cast<const uint*>(tp + u.z);
        uint R3 = *reinterpret_cast<const uint*>(tp + u.w);

        // per-byte count of negative products; bytes <= 4, no carry
        uint P = (R0 ^ K[0]) + (R1 ^ K[1]) + (R2 ^ K[2]) + (R3 ^ K[3]);
        int s0 = __dp4a((int)P, 0x00000001, 0);
        int s1 = __dp4a((int)P, 0x00000100, 0);
        int s2 = __dp4a((int)P, 0x00010000, 0);
        int s3 = __dp4a((int)P, 0x01000000, 0);

        // hv = 4 - 2*s  (exact)
        ull Hlo = fma2(pk2((float)s0, (float)s1), Cm2, C4);
        ull Hhi = fma2(pk2((float)s2, (float)s3), Cm2, C4);

        // a = hv[t-2] at d-2; b = hv[t-1] at d-1
        ull a_lo = __shfl_up_sync(0xffffffffu, h2hi, 1);
        ull a_hi = h2lo;
        float h1hx, h1hy, h1lx, h1ly;
        up2(h1hi, h1hx, h1hy);
        up2(h1lo, h1lx, h1ly);
        float bl0 = __shfl_up_sync(0xffffffffu, h1hy, 1);
        ull b_lo = pk2(bl0, h1lx);
        ull b_hi = pk2(h1ly, h1hx);

        acclo = fma2(mul2(a_lo, b_lo), Hlo, acclo);  // zero history -> first 2 iters add 0
        acchi = fma2(mul2(a_hi, b_hi), Hhi, acchi);

        h2lo = h1lo; h2hi = h1hi;
        h1lo = Hlo;  h1hi = Hhi;
    }

    // transposed scatter: g_partial[d][ct]. lane0 owns only its hi pair.
    float alx, aly, ahx, ahy;
    up2(acclo, alx, aly);
    up2(acchi, ahx, ahy);
    if (lane == 0) {
        g_partial[(p0 + 2) * NT + ct] = ahx;
        g_partial[(p0 + 3) * NT + ct] = ahy;
    } else if (p0 < HDC_D) {
        g_partial[(p0    ) * NT + ct] = alx;
        g_partial[(p0 + 1) * NT + ct] = aly;
        g_partial[(p0 + 2) * NT + ct] = ahx;
        g_partial[(p0 + 3) * NT + ct] = ahy;
    }
}

__global__ void __launch_bounds__(128)
final_kernel(float* __restrict__ out) {
    int d = blockIdx.x * blockDim.x + threadIdx.x;
    if (d >= HDC_D) return;

    const float4* pp = reinterpret_cast<const float4*>(g_partial + d * NT);
    float s = 0.0f;
    #pragma unroll
    for (int c = 0; c < NT / 4; c++) {
        float4 a = pp[c];
        s += (a.x + a.y) + (a.z + a.w);   // exact integers -> any order
    }
    float o = s * g_factor[d];            // sign-exact vs reference ordering
    out[d] = (o > 0.0f) ? 1.0f : -1.0f;
}

extern "C" void kernel_launch(void* const* d_in, const int* in_sizes, int n_in,
                              void* d_out, int out_size) {
    const float* inp   = (const float*)d_in[0];
    const float* feat  = (const float*)d_in[1];
    const float* keys  = (const float*)d_in[2];
    const float* level = (const float*)d_in[3];
    const float* W3    = (const float*)d_in[4];
    const float* b3    = (const float*)d_in[5];
    const float* W6    = (const float*)d_in[6];
    const float* b6    = (const float*)d_in[7];
    float* out = (float*)d_out;

    fused_kernel<<<HV_BLOCKS + FAC_BLOCKS, TPB>>>(inp, keys, level,
                                                  feat, W3, b3, W6, b6);
    final_kernel<<<(HDC_D + 127) / 128, 128>>>(out);
}

// round 13
// speedup vs baseline: 1.1664x; 1.0154x over previous
#include <cuda_runtime.h>
#include <math.h>

#define HDC_D      10000
#define HDC_T      2048
#define HDC_LEVELS 100
#define TPB        256     // 8 warps share one tile; each warp = distinct time-chunk
#define WCOLS      128     // columns per block tile (4 per thread)
#define EFFC       126     // effective output columns per block (2-col halo)
#define NBD        80      // ceil(10000 / 126)
#define NTY        5       // y-blocks (time) per column group
#define MTOT       2046    // T - 2 product terms
#define MCHUNK     52      // terms per chunk (52*40 = 2080 >= 2046)
#define SIDX_N     (8 * MCHUNK + 2)   // 418 idx rows staged per block

// per-column accumulator (exact small integers in fp32 -> atomicAdd is
// order-independent and therefore deterministic). Reset by the last block
// of each column group every run, so graph replays see a clean state.
__device__ float g_sum[HDC_D];
__device__ int   g_count[NBD];

typedef unsigned long long ull;
typedef unsigned int uint;

// ---------- packed f32x2 helpers (Blackwell) ----------
__device__ __forceinline__ ull pk2(float lo, float hi) {
    ull r; asm("mov.b64 %0, {%1, %2};" : "=l"(r) : "f"(lo), "f"(hi)); return r;
}
__device__ __forceinline__ void up2(ull v, float& lo, float& hi) {
    asm("mov.b64 {%0, %1}, %2;" : "=f"(lo), "=f"(hi) : "l"(v));
}
__device__ __forceinline__ ull fma2(ull a, ull b, ull c) {
    ull d; asm("fma.rn.f32x2 %0, %1, %2, %3;" : "=l"(d) : "l"(a), "l"(b), "l"(c)); return d;
}
__device__ __forceinline__ ull mul2(ull a, ull b) {
    ull d; asm("mul.rn.f32x2 %0, %1, %2;" : "=l"(d) : "l"(a), "l"(b)); return d;
}

__device__ __forceinline__ int wrapD(int g) {
    if (g < 0)       g += HDC_D;
    if (g >= HDC_D)  g -= HDC_D;
    return g;
}

__global__ void __launch_bounds__(TPB, 3)
hdc_kernel(const float* __restrict__ inp,
           const float* __restrict__ keys,
           const float* __restrict__ level,
           const float* __restrict__ feat,
           const float* __restrict__ W3,
           const float* __restrict__ b3,
           const float* __restrict__ W6,
           const float* __restrict__ b6,
           float* __restrict__ out) {
    __shared__ unsigned char tile8[HDC_LEVELS * WCOLS];  // level sign bytes
    __shared__ ushort4 sidx[SIDX_N];
    __shared__ int s_last;

    const int tid  = threadIdx.x;
    const int warp = tid >> 5;
    const int lane = tid & 31;
    const int bx   = blockIdx.x % NBD;
    const int by   = blockIdx.x / NBD;

    // --- fused idx prep: this block's t-slice -> shared, pre-scaled by 128 B ---
    const int t_base = 8 * MCHUNK * by;
    const int scnt   = min(SIDX_N, HDC_T - t_base);
    for (int i = tid; i < scnt; i += TPB) {
        float4 v = reinterpret_cast<const float4*>(inp)[t_base + i];
        // jnp.round = round half to even -> __float2int_rn
        int i0 = min(max(__float2int_rn(v.x * 99.0f), 0), 99);
        int i1 = min(max(__float2int_rn(v.y * 99.0f), 0), 99);
        int i2 = min(max(__float2int_rn(v.z * 99.0f), 0), 99);
        int i3 = min(max(__float2int_rn(v.w * 99.0f), 0), 99);
        sidx[i] = make_ushort4((unsigned short)(i0 * WCOLS), (unsigned short)(i1 * WCOLS),
                               (unsigned short)(i2 * WCOLS), (unsigned short)(i3 * WCOLS));
    }

    // --- stage 100 x 128 sign-byte tile ---
    const int gstart = bx * EFFC - 2;   // even
    for (int i = tid; i < HDC_LEVELS * (WCOLS / 4); i += TPB) {
        int row = i >> 5;
        int q   = i & 31;
        int ga = wrapD(gstart + 4 * q);
        int gb = wrapD(gstart + 4 * q + 2);
        float2 A = *reinterpret_cast<const float2*>(level + row * HDC_D + ga);
        float2 B = *reinterpret_cast<const float2*>(level + row * HDC_D + gb);
        uint w =  (__float_as_uint(A.x) >> 31)
               | ((__float_as_uint(A.y) >> 31) << 8)
               | ((__float_as_uint(B.x) >> 31) << 16)
               | ((__float_as_uint(B.y) >> 31) << 24);
        *reinterpret_cast<uint*>(tile8 + row * WCOLS + 4 * q) = w;
    }

    // --- per-thread packed key sign bytes, one word per channel ---
    const int p0 = gstart + 4 * lane;   // even
    uint K[4];
    #pragma unroll
    for (int c = 0; c < 4; c++) {
        uint w = 0;
        #pragma unroll
        for (int j = 0; j < 4; j++) {
            int col = wrapD(p0 + j);
            w |= (__float_as_uint(keys[c * HDC_D + col]) >> 31) << (8 * j);
        }
        K[c] = w;
    }
    __syncthreads();

    const int ct    = by * 8 + warp;
    const int m0    = ct * MCHUNK;
    const int iters = min(MCHUNK, MTOT - m0) + 2;
    const int soff  = warp * MCHUNK;
    const unsigned char* tp = tile8 + 4 * lane;

    const ull Cm2 = pk2(-2.0f, -2.0f);
    const ull C4  = pk2( 4.0f,  4.0f);

    ull h1lo = 0, h1hi = 0, h2lo = 0, h2hi = 0, acclo = 0, acchi = 0;

    #pragma unroll 4
    for (int j = 0; j < iters; j++) {
        ushort4 u = sidx[soff + j];             // broadcast LDS.64
        uint R0 = *reinterpret_cast<const uint*>(tp + u.x);
        uint R1 = *reinterpret_cast<const uint*>(tp + u.y);
        uint R2 = *reinterpret_cast<const uint*>(tp + u.z);
        uint R3 = *reinterpret_cast<const uint*>(tp + u.w);

        // per-byte count of negative products; bytes <= 4, no carry
        uint P = (R0 ^ K[0]) + (R1 ^ K[1]) + (R2 ^ K[2]) + (R3 ^ K[3]);
        int s0 = __dp4a((int)P, 0x00000001, 0);
        int s1 = __dp4a((int)P, 0x00000100, 0);
        int s2 = __dp4a((int)P, 0x00010000, 0);
        int s3 = __dp4a((int)P, 0x01000000, 0);

        // hv = 4 - 2*s  (exact)
        ull Hlo = fma2(pk2((float)s0, (float)s1), Cm2, C4);
        ull Hhi = fma2(pk2((float)s2, (float)s3), Cm2, C4);

        // a = hv[t-2] at d-2; b = hv[t-1] at d-1
        ull a_lo = __shfl_up_sync(0xffffffffu, h2hi, 1);
        ull a_hi = h2lo;
        float h1hx, h1hy, h1lx, h1ly;
        up2(h1hi, h1hx, h1hy);
        up2(h1lo, h1lx, h1ly);
        float bl0 = __shfl_up_sync(0xffffffffu, h1hy, 1);
        ull b_lo = pk2(bl0, h1lx);
        ull b_hi = pk2(h1ly, h1hx);

        acclo = fma2(mul2(a_lo, b_lo), Hlo, acclo);  // zero history -> first 2 iters add 0
        acchi = fma2(mul2(a_hi, b_hi), Hhi, acchi);

        h2lo = h1lo; h2hi = h1hi;
        h1lo = Hlo;  h1hi = Hhi;
    }

    // --- accumulate owned columns: c in [gstart+2, gstart+128) and c < D.
    //     (columns >= D are circular duplicates owned by bx=0 -> dropped)
    {
        float a[4];
        up2(acclo, a[0], a[1]);
        up2(acchi, a[2], a[3]);
        #pragma unroll
        for (int j = 0; j < 4; j++) {
            int c = p0 + j;
            if (c >= gstart + 2 && c < HDC_D) atomicAdd(&g_sum[c], a[j]);
        }
    }

    // --- last-arriving y-block for this bx does the trig epilogue ---
    __threadfence();
    __syncthreads();
    if (tid == 0) {
        s_last = (atomicAdd(&g_count[bx], 1) == NTY - 1) ? 1 : 0;
    }
    __syncthreads();
    if (!s_last) return;

    const int cstart = bx * EFFC;
    const int cend   = min(cstart + EFFC, HDC_D);
    const int d      = cstart + tid;

    if (d < cend) {
        const int S[8] = {0, 9, 12, 15, 18, 21, 24, 27};
        float fv[30];
        #pragma unroll
        for (int i = 0; i < 30; i++) fv[i] = feat[i];

        float s = g_sum[d];
        g_sum[d] = 0.0f;            // restore for next replay

        float h[8];
        #pragma unroll
        for (int k = 0; k < 8; k++) {
            const float* w = W3 + (k * HDC_D + d) * 3;
            float p = w[0] * fv[S[k]] + w[1] * fv[S[k] + 1] + w[2] * fv[S[k] + 2];
            h[k] = cosf(p + b3[k * HDC_D + d]) * sinf(p);
        }
        float p6 = 0.0f;
        #pragma unroll
        for (int i = 0; i < 6; i++) p6 += W6[d * 6 + i] * fv[3 + i];
        float h6 = cosf(p6 + b6[d]) * sinf(p6);

        // product refactored; fp32 multiply sign is exact & association-safe here
        float o = s * h[0];
        o *= (h6 + h[7]);
        o *= (h[1] + h[2]) + h[3];
        o *= (h[4] + h[5]) + h[6];
        out[d] = (o > 0.0f) ? 1.0f : -1.0f;
    }
    if (tid == 0) g_count[bx] = 0;   // restore for next replay
}

extern "C" void kernel_launch(void* const* d_in, const int* in_sizes, int n_in,
                              void* d_out, int out_size) {
    const float* inp   = (const float*)d_in[0];
    const float* feat  = (const float*)d_in[1];
    const float* keys  = (const float*)d_in[2];
    const float* level = (const float*)d_in[3];
    const float* W3    = (const float*)d_in[4];
    const float* b3    = (const float*)d_in[5];
    const float* W6    = (const float*)d_in[6];
    const float* b6    = (const float*)d_in[7];
    float* out = (float*)d_out;

    hdc_kernel<<<NBD * NTY, TPB>>>(inp, keys, level, feat, W3, b3, W6, b6, out);
}